// round 13
// baseline (speedup 1.0000x reference)
#include <cuda_runtime.h>
#include <math.h>

#define NPART 262144
#define NNB   4194304
#define GRID_FB  1024           // framesbond blocks (256 particles each)
#define GRID_ALL 4096           // fused gate+pair: 1024 pairs/block
#define NSLOT   (GRID_FB + GRID_ALL)

// ---------------- static device scratch -------------------------------------
__device__ float4 g_CM[NPART];          // center of mass (gate test)
__device__ float4 g_P0[2 * NPART];      // [2i]=back, [2i+1]=base
__device__ float4 g_REST[4 * NPART];    // [4i]=a1(w=type), [4i+1]=a3, [4i+2]=a2
__device__ double g_part[NSLOT];

// ---------------- constants --------------------------------------------------
#define EXCL_EPS 2.0f
#define PI_F 3.14159265358979f
#define SHIFT_STCK 0.90290461f   // (exp(-6*0.5)-1)^2
#define SHIFT_HYDR 0.88207775f   // (exp(-8*0.35)-1)^2
#define GATE_D2 0.613089f        // 0.783^2 : exact gate for hb/crst/coax
#define R2CUT 2.5100f            // (1.5843)^2 : CM gate (0.783 + 2*0.4 slack)

// ---------------- forked-capture resources (created pre-main, no device alloc APIs)
static cudaStream_t g_sB;
static cudaEvent_t  g_evFork, g_evJoin;
namespace { struct StreamInit {
    StreamInit() {
        cudaStreamCreateWithFlags(&g_sB, cudaStreamNonBlocking);
        cudaEventCreateWithFlags(&g_evFork, cudaEventDisableTiming);
        cudaEventCreateWithFlags(&g_evJoin, cudaEventDisableTiming);
    }
} s_streamInit; }

// ---------------- potential pieces -------------------------------------------
__device__ __forceinline__ float acosc(float c) {
    return acosf(fminf(fmaxf(c, -0.999999f), 0.999999f));
}

__device__ __forceinline__ float fexcl_d2(float d2, float sig2, float rstar2,
                                          float b, float rc, float rc2) {
    if (d2 >= rc2) return 0.f;
    if (d2 < rstar2) {
        float s2 = __fdividef(sig2, d2);
        float s6 = s2 * s2 * s2;
        return 4.f * EXCL_EPS * (s6 * s6 - s6);
    }
    float x = sqrtf(d2) - rc;
    return EXCL_EPS * b * x * x;
}

__device__ __forceinline__ float f1f(float r, float a, float r0, float shift,
                                     float rlow, float rhigh, float blow, float rclow,
                                     float bhigh, float rchigh) {
    if (r > rlow && r < rhigh) {
        float ex = __expf(-a * (r - r0)) - 1.f;
        return ex * ex - shift;
    }
    if (r > rclow && r <= rlow) { float x = r - rclow;  return blow  * x * x; }
    if (r >= rhigh && r < rchigh) { float x = r - rchigh; return bhigh * x * x; }
    return 0.f;
}

__device__ __forceinline__ float f2f(float r, float k, float r0, float rc,
                                     float rlow, float rhigh, float blow, float rclow,
                                     float bhigh, float rchigh) {
    if (r > rlow && r < rhigh) {
        float x = r - r0, y = rc - r0;
        return 0.5f * k * (x * x - y * y);
    }
    if (r > rclow && r <= rlow) { float x = r - rclow;  return k * blow  * x * x; }
    if (r >= rhigh && r < rchigh) { float x = r - rchigh; return k * bhigh * x * x; }
    return 0.f;
}

__device__ __forceinline__ float f4f(float th, float a, float t0, float ts, float b, float tc) {
    float dt = fabsf(th - t0);
    if (dt < ts) return 1.f - a * dt * dt;
    if (dt < tc) { float x = tc - dt; return b * x * x; }
    return 0.f;
}

__device__ __forceinline__ float f5f(float x) {
    if (x > 0.f) return 1.f;
    if (x > -0.65f) return 1.f - 2.f * x * x;
    if (x > -0.769231f) { float t = -0.769231f - x; return 10.9032f * t * t; }
    return 0.f;
}

// block-wide float reduction -> ONE plain store to this block's partial slot
__device__ __forceinline__ void block_accum_slot(float v, double* slot) {
    #pragma unroll
    for (int o = 16; o > 0; o >>= 1) v += __shfl_down_sync(0xffffffffu, v, o);
    __shared__ float sw[32];
    int lane = threadIdx.x & 31, warp = threadIdx.x >> 5;
    if (lane == 0) sw[warp] = v;
    __syncthreads();
    if (warp == 0) {
        int nw = (blockDim.x + 31) >> 5;
        float t = (lane < nw) ? sw[lane] : 0.f;
        #pragma unroll
        for (int o = 16; o > 0; o >>= 1) t += __shfl_down_sync(0xffffffffu, t, o);
        if (lane == 0) *slot = (double)t;
    }
}

// ---------------- helpers -----------------------------------------------------
struct Frame { float3 a1, a2, a3; float3 p; };

__device__ __forceinline__ Frame make_frame(const float* __restrict__ pos,
                                            const float4* __restrict__ quat4, int i) {
    float4 q = __ldg(&quat4[i]);
    float w = q.x, x = q.y, y = q.z, z = q.w;
    float inv = rsqrtf(w*w + x*x + y*y + z*z + 1e-12f);
    w *= inv; x *= inv; y *= inv; z *= inv;
    Frame f;
    f.a1 = make_float3(1.f - 2.f*(y*y + z*z), 2.f*(x*y + w*z), 2.f*(x*z - w*y));
    f.a2 = make_float3(2.f*(x*y - w*z), 1.f - 2.f*(x*x + z*z), 2.f*(y*z + w*x));
    f.a3 = make_float3(2.f*(x*z + w*y), 2.f*(y*z - w*x), 1.f - 2.f*(x*x + y*y));
    f.p  = make_float3(__ldg(&pos[3*i]), __ldg(&pos[3*i+1]), __ldg(&pos[3*i+2]));
    return f;
}

// ---------------- kernels -----------------------------------------------------
// Critical-path prelude: CM repack (gate input) only.
__global__ void k_cm(const float* __restrict__ pos, int n) {
    int i = blockIdx.x * blockDim.x + threadIdx.x;
    if (i >= n) return;
    g_CM[i] = make_float4(pos[3*i], pos[3*i+1], pos[3*i+2], 0.f);
}

// Fused frames + bonded (forked stream; must finish before k_all).
__global__ __launch_bounds__(256)
void k_framesbond(const float* __restrict__ pos, const float* __restrict__ quat,
                  const int* __restrict__ types, const float* __restrict__ seps,
                  int n, int nb) {
    __shared__ float4 sP0[514];    // back,base for 257 particles
    __shared__ float4 sST[257];
    __shared__ float4 sA3[257];
    __shared__ float4 sA2[257];
    const int t = threadIdx.x;
    const int pbase = blockIdx.x << 8;
    const int p = pbase + t;
    const float4* quat4 = (const float4*)quat;

    if (p < n) {
        Frame f = make_frame(pos, quat4, p);
        float4 bk = make_float4(f.p.x - 0.4f*f.a1.x, f.p.y - 0.4f*f.a1.y, f.p.z - 0.4f*f.a1.z, 0.f);
        float4 bs = make_float4(f.p.x + 0.4f*f.a1.x, f.p.y + 0.4f*f.a1.y, f.p.z + 0.4f*f.a1.z, 0.f);
        float4 st = make_float4(f.p.x + 0.34f*f.a1.x, f.p.y + 0.34f*f.a1.y, f.p.z + 0.34f*f.a1.z, 0.f);
        float4 a1v = make_float4(f.a1.x, f.a1.y, f.a1.z, __int_as_float(__ldg(&types[p])));
        float4 a3v = make_float4(f.a3.x, f.a3.y, f.a3.z, 0.f);
        float4 a2v = make_float4(f.a2.x, f.a2.y, f.a2.z, 0.f);
        g_P0[2*p]     = bk;
        g_P0[2*p+1]   = bs;
        g_REST[4*p]   = a1v;
        g_REST[4*p+1] = a3v;
        g_REST[4*p+2] = a2v;
        sP0[2*t] = bk; sP0[2*t+1] = bs;
        sST[t] = st; sA3[t] = a3v; sA2[t] = a2v;
    }
    if (t == 0 && pbase + 256 < n) {
        int q = pbase + 256;
        Frame f = make_frame(pos, quat4, q);
        sP0[512] = make_float4(f.p.x - 0.4f*f.a1.x, f.p.y - 0.4f*f.a1.y, f.p.z - 0.4f*f.a1.z, 0.f);
        sP0[513] = make_float4(f.p.x + 0.4f*f.a1.x, f.p.y + 0.4f*f.a1.y, f.p.z + 0.4f*f.a1.z, 0.f);
        sST[256] = make_float4(f.p.x + 0.34f*f.a1.x, f.p.y + 0.34f*f.a1.y, f.p.z + 0.34f*f.a1.z, 0.f);
        sA3[256] = make_float4(f.a3.x, f.a3.y, f.a3.z, 0.f);
        sA2[256] = make_float4(f.a2.x, f.a2.y, f.a2.z, 0.f);
    }
    __syncthreads();

    int k = p;                       // bonded pair (k, k+1)
    float e = 0.f;
    if (k < nb) {
        float4 BKi = sP0[2*t],   BKj = sP0[2*t+2];
        float4 BSi = sP0[2*t+1], BSj = sP0[2*t+3];
        float4 STi = sST[t], STj = sST[t+1];
        float4 A3i = sA3[t], A3j = sA3[t+1];
        float4 A2i = sA2[t], A2j = sA2[t+1];

        // FENE (back-back)
        float dbx = BKj.x - BKi.x, dby = BKj.y - BKi.y, dbz = BKj.z - BKi.z;
        float rb2 = dbx*dbx + dby*dby + dbz*dbz + 1e-12f;
        float rb = sqrtf(rb2);
        float u = (rb - 0.7525f) * 4.f;
        float arg = fminf(u * u, 1.f - 1e-6f);
        e += -log1pf(-arg);

        // bonded excluded volume
        {
            float dx = BSj.x - BSi.x, dy = BSj.y - BSi.y, dz = BSj.z - BSi.z;
            float d2 = dx*dx + dy*dy + dz*dz + 1e-12f;
            e += fexcl_d2(d2, 0.1089f, 0.1024f, 4119.70450017f,
                          0.335388426126f, 0.335388426126f*0.335388426126f);
        }
        {
            float dx = BSj.x - BKi.x, dy = BSj.y - BKi.y, dz = BSj.z - BKi.z;
            float d2 = dx*dx + dy*dy + dz*dz + 1e-12f;
            e += fexcl_d2(d2, 0.265225f, 0.25f, 2047.42812499f,
                          0.52329943261f, 0.52329943261f*0.52329943261f);
        }
        {
            float dx = BKj.x - BSi.x, dy = BKj.y - BSi.y, dz = BKj.z - BSi.z;
            float d2 = dx*dx + dy*dy + dz*dz + 1e-12f;
            e += fexcl_d2(d2, 0.265225f, 0.25f, 2047.42812499f,
                          0.52329943261f, 0.52329943261f*0.52329943261f);
        }

        // stacking
        float dsx = STj.x - STi.x, dsy = STj.y - STi.y, dsz = STj.z - STi.z;
        float d2 = dsx*dsx + dsy*dsy + dsz*dsz + 1e-12f;
        float r = sqrtf(d2);
        float invr = rsqrtf(d2);
        float rhx = dsx*invr, rhy = dsy*invr, rhz = dsz*invr;
        float t4 = acosc(A3i.x*A3j.x + A3i.y*A3j.y + A3i.z*A3j.z);
        float t5 = acosc(A3j.x*rhx + A3j.y*rhy + A3j.z*rhz);
        float t6 = acosc(-(A3i.x*rhx + A3i.y*rhy + A3i.z*rhz));
        float invrb = rsqrtf(rb2);
        float rbhx = dbx*invrb, rbhy = dby*invrb, rbhz = dbz*invrb;
        float cphi1 = A2i.x*rbhx + A2i.y*rbhy + A2i.z*rbhz;
        float cphi2 = A2j.x*rbhx + A2j.y*rbhy + A2j.z*rbhz;
        float f1s = f1f(r, 6.0f, 0.4f, SHIFT_STCK, 0.32f, 0.75f, -0.68f, 0.26f, -12.6f, 0.8f);
        e += __ldg(&seps[k]) * f1s
           * f4f(t4, 1.3f, 0.f, 0.8f, 6.4f, 0.961538f)
           * f4f(t5, 0.9f, 0.f, 0.95f, 3.9f, 1.16959f)
           * f4f(t6, 0.9f, 0.f, 0.95f, 3.9f, 1.16959f)
           * f5f(cphi1) * f5f(cphi2);
    }
    block_accum_slot(e, &g_part[blockIdx.x]);
}

// One survivor pair: excl (exact) + predicated angular block. stck derived.
__device__ __forceinline__ float pair_energy(int2 pr, const float* __restrict__ heps) {
    int i = pr.x, j = pr.y;
    float4 bk_i = __ldg(&g_P0[2*i]), bs_i = __ldg(&g_P0[2*i+1]);
    float4 bk_j = __ldg(&g_P0[2*j]), bs_j = __ldg(&g_P0[2*j+1]);
    float e = 0.f;

    float dx = bs_j.x - bs_i.x, dy = bs_j.y - bs_i.y, dz = bs_j.z - bs_i.z;
    float d2bb = dx*dx + dy*dy + dz*dz + 1e-12f;

    float ex2 = bk_j.x - bk_i.x, ey2 = bk_j.y - bk_i.y, ez2 = bk_j.z - bk_i.z;
    float d2kk = ex2*ex2 + ey2*ey2 + ez2*ez2 + 1e-12f;

    float mx = bs_j.x - bk_i.x, my = bs_j.y - bk_i.y, mz = bs_j.z - bk_i.z;
    float d2m1 = mx*mx + my*my + mz*mz + 1e-12f;

    float nx = bk_j.x - bs_i.x, ny = bk_j.y - bs_i.y, nz = bk_j.z - bs_i.z;
    float d2m2 = nx*nx + ny*ny + nz*nz + 1e-12f;

    e += fexcl_d2(d2kk, 0.49f, 0.455625f, 892.016223343f,
                  0.711879214356f, 0.711879214356f*0.711879214356f);
    e += fexcl_d2(d2bb, 0.1089f, 0.1024f, 4119.70450017f,
                  0.335388426126f, 0.335388426126f*0.335388426126f);
    e += fexcl_d2(d2m1, 0.265225f, 0.25f, 2047.42812499f,
                  0.52329943261f, 0.52329943261f*0.52329943261f);
    e += fexcl_d2(d2m2, 0.265225f, 0.25f, 2047.42812499f,
                  0.52329943261f, 0.52329943261f*0.52329943261f);

    if (d2bb < GATE_D2) {
        float4 A1i = __ldg(&g_REST[4*i]),   A1j = __ldg(&g_REST[4*j]);
        float4 A3i = __ldg(&g_REST[4*i+1]), A3j = __ldg(&g_REST[4*j+1]);

        float r = sqrtf(d2bb);
        float f1h = f1f(r, 8.0f, 0.4f, SHIFT_HYDR, 0.34f, 0.7f, -126.2f, 0.276f, -7.87f, 0.783f);
        float f2c = f2f(r, 47.5f, 0.575f, 0.675f, 0.495f, 0.655f, -0.888f, 0.45f, -0.888f, 0.68f);

        float t1 = acosc(-(A1i.x*A1j.x + A1i.y*A1j.y + A1i.z*A1j.z));
        float t4 = acosc(A3i.x*A3j.x + A3i.y*A3j.y + A3i.z*A3j.z);

        if (f1h != 0.f || f2c != 0.f) {
            float invr = rsqrtf(d2bb);
            float rhx = dx*invr, rhy = dy*invr, rhz = dz*invr;
            float t2 = acosc(-(A1j.x*rhx + A1j.y*rhy + A1j.z*rhz));
            float t3 = acosc(A1i.x*rhx + A1i.y*rhy + A1i.z*rhz);
            float t7 = acosc(-(A3j.x*rhx + A3j.y*rhy + A3j.z*rhz));
            float t8 = acosc(A3i.x*rhx + A3i.y*rhy + A3i.z*rhz);
            float f4t7  = f4f(t7,        4.0f, 1.5707963267948966f, 0.45f, 17.0526f, 0.555556f);
            float f4t7m = f4f(PI_F - t7, 4.0f, 1.5707963267948966f, 0.45f, 17.0526f, 0.555556f);
            if (f1h != 0.f) {
                int bti = __float_as_int(A1i.w), btj = __float_as_int(A1j.w);
                float eps = __ldg(&heps[bti * 4 + btj]);
                e += eps * f1h
                   * f4f(t1, 1.5f, 0.f, 0.7f, 4.16038f, 0.952381f)
                   * f4f(t2, 1.5f, 0.f, 0.7f, 4.16038f, 0.952381f)
                   * f4f(t3, 1.5f, 0.f, 0.7f, 4.16038f, 0.952381f)
                   * f4f(t4, 0.46f, PI_F, 0.7f, 1.14813f, 3.0f)
                   * f4t7
                   * f4f(t8, 4.0f, 1.5707963267948966f, 0.45f, 17.0526f, 0.555556f);
            }
            if (f2c != 0.f) {
                e += f2c
                   * f4f(t1, 2.25f, 0.791592653589793f, 0.58f, 10.9032f, 0.766284f)
                   * f4f(t4, 1.5f, 0.f, 0.7f, 4.16038f, 0.952381f)
                   * (f4t7 + f4t7m);
            }
        }

        // coaxial stacking: stck diff derived from base diff and a1 diff
        float dcx = dx - 0.06f*(A1j.x - A1i.x);
        float dcy = dy - 0.06f*(A1j.y - A1i.y);
        float dcz = dz - 0.06f*(A1j.z - A1i.z);
        float c2 = dcx*dcx + dcy*dcy + dcz*dcz + 1e-12f;
        float rcx = sqrtf(c2);
        float f2x = f2f(rcx, 46.0f, 0.4f, 0.6f, 0.22f, 0.58f, -0.7f, 0.2f, -0.7f, 0.62f);
        if (f2x != 0.f) {
            float4 A2i = __ldg(&g_REST[4*i+2]), A2j = __ldg(&g_REST[4*j+2]);
            float invc = rsqrtf(c2);
            float ct5 = acosc(A3j.x*dcx*invc + A3j.y*dcy*invc + A3j.z*dcz*invc);
            float cphi3 = A2i.x*A2j.x + A2i.y*A2j.y + A2i.z*A2j.z;
            e += f2x
               * f4f(t1, 2.0f, 2.592f, 0.65f, 10.9032f, 0.766284f)
               * f4f(t4, 1.3f, 0.f, 0.8f, 6.4f, 0.961538f)
               * f4f(ct5, 0.9f, 0.f, 0.95f, 3.9f, 1.16959f)
               * f5f(cphi3);
        }
    }
    return e;
}

// Fused gate + pair: 4 pairs/thread, CM loads front-batched; survivors
// evaluated inline (no list, no atomics, one fewer launch).
__global__ __launch_bounds__(256)
void k_all(const int* __restrict__ nbp, const float* __restrict__ heps, int nnb) {
    const int t = threadIdx.x;
    const int tile = blockIdx.x * 1024;
    const int2* p2 = (const int2*)nbp;

    int2 pr[4];
    float4 ci[4], cj[4];
    #pragma unroll
    for (int k = 0; k < 4; k++) {
        int idx = tile + k * 256 + t;
        pr[k] = (idx < nnb) ? __ldg(&p2[idx]) : make_int2(0, 0);
    }
    #pragma unroll
    for (int k = 0; k < 4; k++) {
        ci[k] = __ldg(&g_CM[pr[k].x]);
        cj[k] = __ldg(&g_CM[pr[k].y]);
    }

    float e = 0.f;
    #pragma unroll
    for (int k = 0; k < 4; k++) {
        int idx = tile + k * 256 + t;
        float dx = cj[k].x - ci[k].x, dy = cj[k].y - ci[k].y, dz = cj[k].z - ci[k].z;
        float d2 = dx*dx + dy*dy + dz*dz;
        if (d2 < R2CUT && idx < nnb)
            e += pair_energy(pr[k], heps);
    }
    block_accum_slot(e, &g_part[GRID_FB + blockIdx.x]);
}

__global__ void k_final(float* __restrict__ out) {
    __shared__ double sd[256];
    double s = 0.0;
    for (int i = threadIdx.x; i < NSLOT; i += 256) s += g_part[i];
    sd[threadIdx.x] = s;
    __syncthreads();
    for (int o = 128; o > 0; o >>= 1) {
        if (threadIdx.x < o) sd[threadIdx.x] += sd[threadIdx.x + o];
        __syncthreads();
    }
    if (threadIdx.x == 0) out[0] = (float)sd[0];
}

// ---------------- launch -------------------------------------------------------
extern "C" void kernel_launch(void* const* d_in, const int* in_sizes, int n_in,
                              void* d_out, int out_size) {
    const float* pos   = (const float*)d_in[0];
    const float* quat  = (const float*)d_in[1];
    const float* seps  = (const float*)d_in[2];
    const float* heps  = (const float*)d_in[3];
    const int*   nbp   = (const int*)d_in[6];
    const int*   types = (const int*)d_in[7];

    int n   = in_sizes[0] / 3;
    int nb  = in_sizes[5] / 2;
    int nnb = in_sizes[6] / 2;
    if (n > NPART) n = NPART;
    if (nnb > NNB) nnb = NNB;

    // fork: frames+bonded on stream B, CM repack on main, then join
    cudaEventRecord(g_evFork, 0);
    cudaStreamWaitEvent(g_sB, g_evFork, 0);
    k_framesbond<<<GRID_FB, 256, 0, g_sB>>>(pos, quat, types, seps, n, nb);
    cudaEventRecord(g_evJoin, g_sB);

    k_cm<<<(n + 255) / 256, 256>>>(pos, n);

    // fused gate+pair needs P0/REST (stream B) and CM (main)
    cudaStreamWaitEvent(0, g_evJoin, 0);
    k_all<<<GRID_ALL, 256>>>(nbp, heps, nnb);
    k_final<<<1, 256>>>((float*)d_out);
}

// round 14
// speedup vs baseline: 1.8364x; 1.8364x over previous
#include <cuda_runtime.h>
#include <math.h>

#define NPART 262144
#define NNB   4194304
#define GRID_FB 1024            // framesbond blocks (256 particles each)
#define GRID_P2 2048            // pair grid
#define NSLOT   (GRID_FB + GRID_P2)   // 3072 partial slots
#define SLOT_PER_THREAD (NSLOT / 256) // 12

// ---------------- static device scratch -------------------------------------
__device__ float4 g_CM[NPART];          // center of mass (gate only)
__device__ float4 g_P0[2 * NPART];      // [2i]=back, [2i+1]=base
__device__ float4 g_REST[4 * NPART];    // [4i]=a1(w=type), [4i+1]=a3, [4i+2]=a2
__device__ int2   g_list[NNB];
__device__ int    g_count;
__device__ double g_part[NSLOT];

// ---------------- constants --------------------------------------------------
#define EXCL_EPS 2.0f
#define PI_F 3.14159265358979f
#define SHIFT_STCK 0.90290461f   // (exp(-6*0.5)-1)^2
#define SHIFT_HYDR 0.88207775f   // (exp(-8*0.35)-1)^2
#define GATE_D2 0.613089f        // 0.783^2 : exact gate for hb/crst/coax
#define R2CUT 2.5100f            // (1.5843)^2 : CM gate (0.783 + 2*0.4 slack)

// ---------------- forked-capture resources (created pre-main, no device alloc APIs)
static cudaStream_t g_sB;
static cudaEvent_t  g_evFork, g_evJoin;
namespace { struct StreamInit {
    StreamInit() {
        cudaStreamCreateWithFlags(&g_sB, cudaStreamNonBlocking);
        cudaEventCreateWithFlags(&g_evFork, cudaEventDisableTiming);
        cudaEventCreateWithFlags(&g_evJoin, cudaEventDisableTiming);
    }
} s_streamInit; }

// ---------------- potential pieces -------------------------------------------
__device__ __forceinline__ float acosc(float c) {
    return acosf(fminf(fmaxf(c, -0.999999f), 0.999999f));
}

__device__ __forceinline__ float fexcl_d2(float d2, float sig2, float rstar2,
                                          float b, float rc, float rc2) {
    if (d2 >= rc2) return 0.f;
    if (d2 < rstar2) {
        float s2 = __fdividef(sig2, d2);
        float s6 = s2 * s2 * s2;
        return 4.f * EXCL_EPS * (s6 * s6 - s6);
    }
    float x = sqrtf(d2) - rc;
    return EXCL_EPS * b * x * x;
}

__device__ __forceinline__ float f1f(float r, float a, float r0, float shift,
                                     float rlow, float rhigh, float blow, float rclow,
                                     float bhigh, float rchigh) {
    if (r > rlow && r < rhigh) {
        float ex = __expf(-a * (r - r0)) - 1.f;
        return ex * ex - shift;
    }
    if (r > rclow && r <= rlow) { float x = r - rclow;  return blow  * x * x; }
    if (r >= rhigh && r < rchigh) { float x = r - rchigh; return bhigh * x * x; }
    return 0.f;
}

__device__ __forceinline__ float f2f(float r, float k, float r0, float rc,
                                     float rlow, float rhigh, float blow, float rclow,
                                     float bhigh, float rchigh) {
    if (r > rlow && r < rhigh) {
        float x = r - r0, y = rc - r0;
        return 0.5f * k * (x * x - y * y);
    }
    if (r > rclow && r <= rlow) { float x = r - rclow;  return k * blow  * x * x; }
    if (r >= rhigh && r < rchigh) { float x = r - rchigh; return k * bhigh * x * x; }
    return 0.f;
}

__device__ __forceinline__ float f4f(float th, float a, float t0, float ts, float b, float tc) {
    float dt = fabsf(th - t0);
    if (dt < ts) return 1.f - a * dt * dt;
    if (dt < tc) { float x = tc - dt; return b * x * x; }
    return 0.f;
}

__device__ __forceinline__ float f5f(float x) {
    if (x > 0.f) return 1.f;
    if (x > -0.65f) return 1.f - 2.f * x * x;
    if (x > -0.769231f) { float t = -0.769231f - x; return 10.9032f * t * t; }
    return 0.f;
}

// block-wide float reduction -> ONE plain store to this block's partial slot
__device__ __forceinline__ void block_accum_slot(float v, double* slot) {
    #pragma unroll
    for (int o = 16; o > 0; o >>= 1) v += __shfl_down_sync(0xffffffffu, v, o);
    __shared__ float sw[32];
    int lane = threadIdx.x & 31, warp = threadIdx.x >> 5;
    if (lane == 0) sw[warp] = v;
    __syncthreads();
    if (warp == 0) {
        int nw = (blockDim.x + 31) >> 5;
        float t = (lane < nw) ? sw[lane] : 0.f;
        #pragma unroll
        for (int o = 16; o > 0; o >>= 1) t += __shfl_down_sync(0xffffffffu, t, o);
        if (lane == 0) *slot = (double)t;
    }
}

// ---------------- helpers -----------------------------------------------------
struct Frame { float3 a1, a2, a3; float3 p; };

__device__ __forceinline__ Frame make_frame(const float* __restrict__ pos,
                                            const float4* __restrict__ quat4, int i) {
    float4 q = __ldg(&quat4[i]);
    float w = q.x, x = q.y, y = q.z, z = q.w;
    float inv = rsqrtf(w*w + x*x + y*y + z*z + 1e-12f);
    w *= inv; x *= inv; y *= inv; z *= inv;
    Frame f;
    f.a1 = make_float3(1.f - 2.f*(y*y + z*z), 2.f*(x*y + w*z), 2.f*(x*z - w*y));
    f.a2 = make_float3(2.f*(x*y - w*z), 1.f - 2.f*(x*x + z*z), 2.f*(y*z + w*x));
    f.a3 = make_float3(2.f*(x*z + w*y), 2.f*(y*z - w*x), 1.f - 2.f*(x*x + y*y));
    f.p  = make_float3(__ldg(&pos[3*i]), __ldg(&pos[3*i+1]), __ldg(&pos[3*i+2]));
    return f;
}

// ---------------- kernels -----------------------------------------------------
// Critical-path prelude: CM repack (gate input) + counter reset. Nothing else.
__global__ void k_cm(const float* __restrict__ pos, int n) {
    int i = blockIdx.x * blockDim.x + threadIdx.x;
    if (i == 0) g_count = 0;
    if (i >= n) return;
    g_CM[i] = make_float4(pos[3*i], pos[3*i+1], pos[3*i+2], 0.f);
}

// Fused frames + bonded (off critical path, forked stream).
__global__ __launch_bounds__(256)
void k_framesbond(const float* __restrict__ pos, const float* __restrict__ quat,
                  const int* __restrict__ types, const float* __restrict__ seps,
                  int n, int nb) {
    __shared__ float4 sP0[514];    // back,base for 257 particles
    __shared__ float4 sST[257];
    __shared__ float4 sA3[257];
    __shared__ float4 sA2[257];
    const int t = threadIdx.x;
    const int pbase = blockIdx.x << 8;
    const int p = pbase + t;
    const float4* quat4 = (const float4*)quat;

    if (p < n) {
        Frame f = make_frame(pos, quat4, p);
        float4 bk = make_float4(f.p.x - 0.4f*f.a1.x, f.p.y - 0.4f*f.a1.y, f.p.z - 0.4f*f.a1.z, 0.f);
        float4 bs = make_float4(f.p.x + 0.4f*f.a1.x, f.p.y + 0.4f*f.a1.y, f.p.z + 0.4f*f.a1.z, 0.f);
        float4 st = make_float4(f.p.x + 0.34f*f.a1.x, f.p.y + 0.34f*f.a1.y, f.p.z + 0.34f*f.a1.z, 0.f);
        float4 a1v = make_float4(f.a1.x, f.a1.y, f.a1.z, __int_as_float(__ldg(&types[p])));
        float4 a3v = make_float4(f.a3.x, f.a3.y, f.a3.z, 0.f);
        float4 a2v = make_float4(f.a2.x, f.a2.y, f.a2.z, 0.f);
        g_P0[2*p]     = bk;
        g_P0[2*p+1]   = bs;
        g_REST[4*p]   = a1v;
        g_REST[4*p+1] = a3v;
        g_REST[4*p+2] = a2v;
        sP0[2*t] = bk; sP0[2*t+1] = bs;
        sST[t] = st; sA3[t] = a3v; sA2[t] = a2v;
    }
    if (t == 0 && pbase + 256 < n) {
        int q = pbase + 256;
        Frame f = make_frame(pos, quat4, q);
        sP0[512] = make_float4(f.p.x - 0.4f*f.a1.x, f.p.y - 0.4f*f.a1.y, f.p.z - 0.4f*f.a1.z, 0.f);
        sP0[513] = make_float4(f.p.x + 0.4f*f.a1.x, f.p.y + 0.4f*f.a1.y, f.p.z + 0.4f*f.a1.z, 0.f);
        sST[256] = make_float4(f.p.x + 0.34f*f.a1.x, f.p.y + 0.34f*f.a1.y, f.p.z + 0.34f*f.a1.z, 0.f);
        sA3[256] = make_float4(f.a3.x, f.a3.y, f.a3.z, 0.f);
        sA2[256] = make_float4(f.a2.x, f.a2.y, f.a2.z, 0.f);
    }
    __syncthreads();

    int k = p;                       // bonded pair (k, k+1)
    float e = 0.f;
    if (k < nb) {
        float4 BKi = sP0[2*t],   BKj = sP0[2*t+2];
        float4 BSi = sP0[2*t+1], BSj = sP0[2*t+3];
        float4 STi = sST[t], STj = sST[t+1];
        float4 A3i = sA3[t], A3j = sA3[t+1];
        float4 A2i = sA2[t], A2j = sA2[t+1];

        // FENE (back-back)
        float dbx = BKj.x - BKi.x, dby = BKj.y - BKi.y, dbz = BKj.z - BKi.z;
        float rb2 = dbx*dbx + dby*dby + dbz*dbz + 1e-12f;
        float rb = sqrtf(rb2);
        float u = (rb - 0.7525f) * 4.f;
        float arg = fminf(u * u, 1.f - 1e-6f);
        e += -log1pf(-arg);

        // bonded excluded volume
        {
            float dx = BSj.x - BSi.x, dy = BSj.y - BSi.y, dz = BSj.z - BSi.z;
            float d2 = dx*dx + dy*dy + dz*dz + 1e-12f;
            e += fexcl_d2(d2, 0.1089f, 0.1024f, 4119.70450017f,
                          0.335388426126f, 0.335388426126f*0.335388426126f);
        }
        {
            float dx = BSj.x - BKi.x, dy = BSj.y - BKi.y, dz = BSj.z - BKi.z;
            float d2 = dx*dx + dy*dy + dz*dz + 1e-12f;
            e += fexcl_d2(d2, 0.265225f, 0.25f, 2047.42812499f,
                          0.52329943261f, 0.52329943261f*0.52329943261f);
        }
        {
            float dx = BKj.x - BSi.x, dy = BKj.y - BSi.y, dz = BKj.z - BSi.z;
            float d2 = dx*dx + dy*dy + dz*dz + 1e-12f;
            e += fexcl_d2(d2, 0.265225f, 0.25f, 2047.42812499f,
                          0.52329943261f, 0.52329943261f*0.52329943261f);
        }

        // stacking
        float dsx = STj.x - STi.x, dsy = STj.y - STi.y, dsz = STj.z - STi.z;
        float d2 = dsx*dsx + dsy*dsy + dsz*dsz + 1e-12f;
        float r = sqrtf(d2);
        float invr = rsqrtf(d2);
        float rhx = dsx*invr, rhy = dsy*invr, rhz = dsz*invr;
        float t4 = acosc(A3i.x*A3j.x + A3i.y*A3j.y + A3i.z*A3j.z);
        float t5 = acosc(A3j.x*rhx + A3j.y*rhy + A3j.z*rhz);
        float t6 = acosc(-(A3i.x*rhx + A3i.y*rhy + A3i.z*rhz));
        float invrb = rsqrtf(rb2);
        float rbhx = dbx*invrb, rbhy = dby*invrb, rbhz = dbz*invrb;
        float cphi1 = A2i.x*rbhx + A2i.y*rbhy + A2i.z*rbhz;
        float cphi2 = A2j.x*rbhx + A2j.y*rbhy + A2j.z*rbhz;
        float f1s = f1f(r, 6.0f, 0.4f, SHIFT_STCK, 0.32f, 0.75f, -0.68f, 0.26f, -12.6f, 0.8f);
        e += __ldg(&seps[k]) * f1s
           * f4f(t4, 1.3f, 0.f, 0.8f, 6.4f, 0.961538f)
           * f4f(t5, 0.9f, 0.f, 0.95f, 3.9f, 1.16959f)
           * f4f(t6, 0.9f, 0.f, 0.95f, 3.9f, 1.16959f)
           * f5f(cphi1) * f5f(cphi2);
    }
    block_accum_slot(e, &g_part[blockIdx.x]);
}

// Stage 1: pure CM gate. 2 scattered line-touches/pair — the hard floor.
__global__ __launch_bounds__(512)
void k_gate(const int* __restrict__ nbp, int nnb) {
    const int t = threadIdx.x;
    const int lane = t & 31, wid = t >> 5;
    const int tile = blockIdx.x * 2048;
    const int2* p2 = (const int2*)nbp;

    int2 pr[4];
    float4 ci[4], cj[4];
    #pragma unroll
    for (int k = 0; k < 4; k++) {
        int idx = tile + k * 512 + t;
        pr[k] = (idx < nnb) ? __ldg(&p2[idx]) : make_int2(0, 0);
    }
    #pragma unroll
    for (int k = 0; k < 4; k++) {
        ci[k] = __ldg(&g_CM[pr[k].x]);
        cj[k] = __ldg(&g_CM[pr[k].y]);
    }

    unsigned pmask = 0u;
    #pragma unroll
    for (int k = 0; k < 4; k++) {
        int idx = tile + k * 512 + t;
        float dx = cj[k].x - ci[k].x, dy = cj[k].y - ci[k].y, dz = cj[k].z - ci[k].z;
        float d2 = dx*dx + dy*dy + dz*dz;
        if (d2 < R2CUT && idx < nnb) pmask |= 1u << k;
    }

    int cnt = __popc(pmask);
    int scan = cnt;
    #pragma unroll
    for (int o = 1; o < 32; o <<= 1) {
        int v = __shfl_up_sync(0xffffffffu, scan, o);
        if (lane >= o) scan += v;
    }
    __shared__ int s_wb[16];
    __shared__ int s_base;
    if (lane == 31) s_wb[wid] = scan;
    __syncthreads();
    if (t == 0) {
        int s = 0;
        #pragma unroll
        for (int w = 0; w < 16; w++) { int c = s_wb[w]; s_wb[w] = s; s += c; }
        s_base = atomicAdd(&g_count, s);
    }
    __syncthreads();
    int off = s_base + s_wb[wid] + (scan - cnt);
    #pragma unroll
    for (int k = 0; k < 4; k++)
        if (pmask & (1u << k)) g_list[off++] = pr[k];
}

// One survivor pair: excl (exact) + predicated angular block. stck derived.
__device__ __forceinline__ float pair_energy(int2 pr, const float* __restrict__ heps) {
    int i = pr.x, j = pr.y;
    float4 bk_i = __ldg(&g_P0[2*i]), bs_i = __ldg(&g_P0[2*i+1]);
    float4 bk_j = __ldg(&g_P0[2*j]), bs_j = __ldg(&g_P0[2*j+1]);
    float e = 0.f;

    float dx = bs_j.x - bs_i.x, dy = bs_j.y - bs_i.y, dz = bs_j.z - bs_i.z;
    float d2bb = dx*dx + dy*dy + dz*dz + 1e-12f;

    float ex2 = bk_j.x - bk_i.x, ey2 = bk_j.y - bk_i.y, ez2 = bk_j.z - bk_i.z;
    float d2kk = ex2*ex2 + ey2*ey2 + ez2*ez2 + 1e-12f;

    float mx = bs_j.x - bk_i.x, my = bs_j.y - bk_i.y, mz = bs_j.z - bk_i.z;
    float d2m1 = mx*mx + my*my + mz*mz + 1e-12f;

    float nx = bk_j.x - bs_i.x, ny = bk_j.y - bs_i.y, nz = bk_j.z - bs_i.z;
    float d2m2 = nx*nx + ny*ny + nz*nz + 1e-12f;

    e += fexcl_d2(d2kk, 0.49f, 0.455625f, 892.016223343f,
                  0.711879214356f, 0.711879214356f*0.711879214356f);
    e += fexcl_d2(d2bb, 0.1089f, 0.1024f, 4119.70450017f,
                  0.335388426126f, 0.335388426126f*0.335388426126f);
    e += fexcl_d2(d2m1, 0.265225f, 0.25f, 2047.42812499f,
                  0.52329943261f, 0.52329943261f*0.52329943261f);
    e += fexcl_d2(d2m2, 0.265225f, 0.25f, 2047.42812499f,
                  0.52329943261f, 0.52329943261f*0.52329943261f);

    if (d2bb < GATE_D2) {
        float4 A1i = __ldg(&g_REST[4*i]),   A1j = __ldg(&g_REST[4*j]);
        float4 A3i = __ldg(&g_REST[4*i+1]), A3j = __ldg(&g_REST[4*j+1]);

        float r = sqrtf(d2bb);
        float f1h = f1f(r, 8.0f, 0.4f, SHIFT_HYDR, 0.34f, 0.7f, -126.2f, 0.276f, -7.87f, 0.783f);
        float f2c = f2f(r, 47.5f, 0.575f, 0.675f, 0.495f, 0.655f, -0.888f, 0.45f, -0.888f, 0.68f);

        float t1 = acosc(-(A1i.x*A1j.x + A1i.y*A1j.y + A1i.z*A1j.z));
        float t4 = acosc(A3i.x*A3j.x + A3i.y*A3j.y + A3i.z*A3j.z);

        if (f1h != 0.f || f2c != 0.f) {
            float invr = rsqrtf(d2bb);
            float rhx = dx*invr, rhy = dy*invr, rhz = dz*invr;
            float t2 = acosc(-(A1j.x*rhx + A1j.y*rhy + A1j.z*rhz));
            float t3 = acosc(A1i.x*rhx + A1i.y*rhy + A1i.z*rhz);
            float t7 = acosc(-(A3j.x*rhx + A3j.y*rhy + A3j.z*rhz));
            float t8 = acosc(A3i.x*rhx + A3i.y*rhy + A3i.z*rhz);
            float f4t7  = f4f(t7,        4.0f, 1.5707963267948966f, 0.45f, 17.0526f, 0.555556f);
            float f4t7m = f4f(PI_F - t7, 4.0f, 1.5707963267948966f, 0.45f, 17.0526f, 0.555556f);
            if (f1h != 0.f) {
                int bti = __float_as_int(A1i.w), btj = __float_as_int(A1j.w);
                float eps = __ldg(&heps[bti * 4 + btj]);
                e += eps * f1h
                   * f4f(t1, 1.5f, 0.f, 0.7f, 4.16038f, 0.952381f)
                   * f4f(t2, 1.5f, 0.f, 0.7f, 4.16038f, 0.952381f)
                   * f4f(t3, 1.5f, 0.f, 0.7f, 4.16038f, 0.952381f)
                   * f4f(t4, 0.46f, PI_F, 0.7f, 1.14813f, 3.0f)
                   * f4t7
                   * f4f(t8, 4.0f, 1.5707963267948966f, 0.45f, 17.0526f, 0.555556f);
            }
            if (f2c != 0.f) {
                e += f2c
                   * f4f(t1, 2.25f, 0.791592653589793f, 0.58f, 10.9032f, 0.766284f)
                   * f4f(t4, 1.5f, 0.f, 0.7f, 4.16038f, 0.952381f)
                   * (f4t7 + f4t7m);
            }
        }

        // coaxial stacking: stck diff derived from base diff and a1 diff
        float dcx = dx - 0.06f*(A1j.x - A1i.x);
        float dcy = dy - 0.06f*(A1j.y - A1i.y);
        float dcz = dz - 0.06f*(A1j.z - A1i.z);
        float c2 = dcx*dcx + dcy*dcy + dcz*dcz + 1e-12f;
        float rcx = sqrtf(c2);
        float f2x = f2f(rcx, 46.0f, 0.4f, 0.6f, 0.22f, 0.58f, -0.7f, 0.2f, -0.7f, 0.62f);
        if (f2x != 0.f) {
            float4 A2i = __ldg(&g_REST[4*i+2]), A2j = __ldg(&g_REST[4*j+2]);
            float invc = rsqrtf(c2);
            float ct5 = acosc(A3j.x*dcx*invc + A3j.y*dcy*invc + A3j.z*dcz*invc);
            float cphi3 = A2i.x*A2j.x + A2i.y*A2j.y + A2i.z*A2j.z;
            e += f2x
               * f4f(t1, 2.0f, 2.592f, 0.65f, 10.9032f, 0.766284f)
               * f4f(t4, 1.3f, 0.f, 0.8f, 6.4f, 0.961538f)
               * f4f(ct5, 0.9f, 0.f, 0.95f, 3.9f, 1.16959f)
               * f5f(cphi3);
        }
    }
    return e;
}

// Stage 2: two pairs per thread, loads front-batched for MLP.
__global__ __launch_bounds__(256)
void k_pair(const float* __restrict__ heps) {
    int total = g_count;
    int stride = gridDim.x * blockDim.x;
    int tid0 = blockIdx.x * blockDim.x + threadIdx.x;
    float e = 0.f;
    for (int idx = tid0; idx < total; idx += 2 * stride) {
        int idxb = idx + stride;
        int2 pr1 = __ldg(&g_list[idx]);
        if (idxb < total) {
            int2 pr2 = __ldg(&g_list[idxb]);
            e += pair_energy(pr1, heps);
            e += pair_energy(pr2, heps);
        } else {
            e += pair_energy(pr1, heps);
        }
    }
    block_accum_slot(e, &g_part[GRID_FB + blockIdx.x]);
}

// Final reduction: all 12 slot-loads per thread are independent and issued
// before any dependent add (breaks the serial DRAM-latency chain).
__global__ void k_final(float* __restrict__ out) {
    const int t = threadIdx.x;
    double v[SLOT_PER_THREAD];
    #pragma unroll
    for (int k = 0; k < SLOT_PER_THREAD; k++)
        v[k] = g_part[t + k * 256];
    double s = 0.0;
    #pragma unroll
    for (int k = 0; k < SLOT_PER_THREAD; k++) s += v[k];

    // warp reduce (double shuffles), then cross-warp via shared
    #pragma unroll
    for (int o = 16; o > 0; o >>= 1) s += __shfl_down_sync(0xffffffffu, s, o);
    __shared__ double sw[8];
    int lane = t & 31, warp = t >> 5;
    if (lane == 0) sw[warp] = s;
    __syncthreads();
    if (warp == 0) {
        double x = (lane < 8) ? sw[lane] : 0.0;
        #pragma unroll
        for (int o = 4; o > 0; o >>= 1) x += __shfl_down_sync(0xffffffffu, x, o);
        if (lane == 0) out[0] = (float)x;
    }
}

// ---------------- launch -------------------------------------------------------
extern "C" void kernel_launch(void* const* d_in, const int* in_sizes, int n_in,
                              void* d_out, int out_size) {
    const float* pos   = (const float*)d_in[0];
    const float* quat  = (const float*)d_in[1];
    const float* seps  = (const float*)d_in[2];
    const float* heps  = (const float*)d_in[3];
    const int*   nbp   = (const int*)d_in[6];
    const int*   types = (const int*)d_in[7];

    int n   = in_sizes[0] / 3;
    int nb  = in_sizes[5] / 2;
    int nnb = in_sizes[6] / 2;
    if (n > NPART) n = NPART;
    if (nnb > NNB) nnb = NNB;

    // fork: frames+bonded run on stream B, hidden under the gate
    cudaEventRecord(g_evFork, 0);
    cudaStreamWaitEvent(g_sB, g_evFork, 0);
    k_framesbond<<<GRID_FB, 256, 0, g_sB>>>(pos, quat, types, seps, n, nb);
    cudaEventRecord(g_evJoin, g_sB);

    // critical path
    k_cm<<<(n + 255) / 256, 256>>>(pos, n);
    k_gate<<<(nnb + 2047) / 2048, 512>>>(nbp, nnb);

    // join before pair (needs P0/REST from stream B)
    cudaStreamWaitEvent(0, g_evJoin, 0);
    k_pair<<<GRID_P2, 256>>>(heps);
    k_final<<<1, 256>>>((float*)d_out);
}